// round 14
// baseline (speedup 1.0000x reference)
#include <cuda_runtime.h>
#include <cuda_bf16.h>
#include <cuda_fp16.h>
#include <cstdint>
#include <math.h>

// Problem constants
#define BB 2
#define SS 2048
#define DD 1024
#define NH 16
#define HD 64
#define MM (BB*SS)      // 4096
#define QSCALE 0.18033688011112042f   // 0.125 * log2(e)

// ---------------------------------------------------------------------------
// Scratch (device globals)
// ---------------------------------------------------------------------------
__device__ __align__(16) __half g_A16[MM*DD];       // residual fp16
__device__ __align__(16) __half g_A216[MM*DD];      // attn out fp16
__device__ __align__(16) __half g_WQ16[DD*DD];      // pre-scaled by QSCALE
__device__ __align__(16) __half g_WK16[DD*DD];
__device__ __align__(16) __half g_WV16[DD*DD];
__device__ __align__(16) __half g_WO16[DD*DD];      // transposed W_O
__device__ __align__(16) __half g_Q16[BB*NH*SS*HD];
__device__ __align__(16) __half g_K16[BB*NH*SS*HD];
__device__ __align__(16) __half g_V16[BB*NH*SS*HD];
// dataflow flags: [0,768) qkv tiles (z*256+mt*8+ntl); [768,1280) attn ((b*16+qb)*16+n)
__device__ int g_flags[1280];

// ---------------------------------------------------------------------------
// helpers
// ---------------------------------------------------------------------------
__device__ __forceinline__ uint32_t smem_u32(const void* p) {
    uint32_t a;
    asm("{ .reg .u64 t; cvta.to.shared.u64 t, %1; cvt.u32.u64 %0, t; }" : "=r"(a) : "l"(p));
    return a;
}
#define LDSM_X4(r, a) asm volatile("ldmatrix.sync.aligned.m8n8.x4.shared.b16 {%0,%1,%2,%3}, [%4];" \
  : "=r"((r)[0]),"=r"((r)[1]),"=r"((r)[2]),"=r"((r)[3]) : "r"(a))
#define LDSM_X4T(r, a) asm volatile("ldmatrix.sync.aligned.m8n8.x4.trans.shared.b16 {%0,%1,%2,%3}, [%4];" \
  : "=r"((r)[0]),"=r"((r)[1]),"=r"((r)[2]),"=r"((r)[3]) : "r"(a))
#define MMA_F16(d, a, b) asm volatile( \
  "mma.sync.aligned.m16n8k16.row.col.f32.f16.f16.f32 {%0,%1,%2,%3},{%4,%5,%6,%7},{%8,%9},{%0,%1,%2,%3};" \
  : "+f"((d)[0]), "+f"((d)[1]), "+f"((d)[2]), "+f"((d)[3]) \
  : "r"((a)[0]),"r"((a)[1]),"r"((a)[2]),"r"((a)[3]), "r"((b)[0]),"r"((b)[1]))
#define CP_ASYNC16(dst, src) asm volatile("cp.async.cg.shared.global [%0], [%1], 16;" :: "r"(dst), "l"(src))
#define CP_COMMIT() asm volatile("cp.async.commit_group;" ::: "memory")
#define CP_WAIT0()  asm volatile("cp.async.wait_group 0;" ::: "memory")
#define CP_WAIT1()  asm volatile("cp.async.wait_group 1;" ::: "memory")

__device__ __forceinline__ float ex2f(float x) {
    float y; asm("ex2.approx.ftz.f32 %0, %1;" : "=f"(y) : "f"(x)); return y;
}
__device__ __forceinline__ uint32_t pack_h2(float a, float b) {
    uint32_t u;
    asm("{ .reg .f16 lo, hi; cvt.rn.f16.f32 lo, %1; cvt.rn.f16.f32 hi, %2; mov.b32 %0, {lo, hi}; }"
        : "=r"(u) : "f"(a), "f"(b));
    return u;
}
__device__ __forceinline__ void wait_flag(int i) {
    volatile int* f = (volatile int*)&g_flags[i];
    while (*f == 0) { __nanosleep(64); }
}

// ---------------------------------------------------------------------------
// Fused prep + flag reset (one launch, runs before the worker kernel).
// ---------------------------------------------------------------------------
__global__ __launch_bounds__(256) void prep_all(
    const float* __restrict__ residual, const float* __restrict__ W_Q,
    const float* __restrict__ W_K, const float* __restrict__ W_V,
    const float* __restrict__ W_O)
{
    int blk = blockIdx.x;
    if (blk == 0) {
        for (int i = threadIdx.x; i < 1280; i += 256) g_flags[i] = 0;
    }
    if (blk < 3584) {
        const float* src;
        __half* dst;
        float sc = 1.0f;
        int base;
        if (blk < 2048)      { src = residual; dst = g_A16;  base = blk; }
        else if (blk < 2560) { src = W_Q; dst = g_WQ16; base = blk - 2048; sc = QSCALE; }
        else if (blk < 3072) { src = W_K; dst = g_WK16; base = blk - 2560; }
        else                 { src = W_V; dst = g_WV16; base = blk - 3072; }
        int idx = base * 256 + threadIdx.x;
        const float4* s = (const float4*)src + (size_t)idx * 2;
        float4 a0 = s[0], a1 = s[1];
        uint32_t o[4];
        o[0] = pack_h2(a0.x * sc, a0.y * sc);
        o[1] = pack_h2(a0.z * sc, a0.w * sc);
        o[2] = pack_h2(a1.x * sc, a1.y * sc);
        o[3] = pack_h2(a1.z * sc, a1.w * sc);
        ((uint4*)g_A16)[0] = ((uint4*)g_A16)[0];  // no-op placeholder removed below
        ((uint4*)dst)[idx] = *(uint4*)o;
    } else {
        __shared__ float t[32][33];
        int tile = blk - 3584;
        int bx = (tile & 31) * 32;
        int by = (tile >> 5) * 32;
        int tx = threadIdx.x & 31, ty = threadIdx.x >> 5;
        #pragma unroll
        for (int i = 0; i < 4; i++)
            t[ty + 8*i][tx] = W_O[(size_t)(by + ty + 8*i) * DD + bx + tx];
        __syncthreads();
        #pragma unroll
        for (int i = 0; i < 4; i++) {
            float v = t[tx][ty + 8*i];
            g_WO16[(size_t)(bx + ty + 8*i) * DD + by + tx] = __float2half_rn(v);
        }
    }
}

// ---------------------------------------------------------------------------
// GEMM body 128x128: C tile = A[128xK] * B[128xK]^T, fp16 in, fp32 acc.
// o16 != nullptr: scatter fp16 to [b,n,p,h]; else fp32 row-major to of.
// ---------------------------------------------------------------------------
#define ROWB 80
#define MATB (128*ROWB)
#define STAGEB (2*MATB)

__device__ __forceinline__ void gemm_body(char* smem,
    const __half* __restrict__ A, const __half* __restrict__ B,
    int m0, int n0, __half* __restrict__ o16, float* __restrict__ of)
{
    const int tid = threadIdx.x, lane = tid & 31, wid = tid >> 5;
    const int wm = wid & 3, wn = wid >> 2;
    const __half* gsrc[2] = { A, B };

    const uint32_t sbase = smem_u32(smem);
    const int lrow = tid >> 2;
    const int lseg = tid & 3;
    const int g = lane >> 3, rl = lane & 7;

    float acc[2][8][4];
    #pragma unroll
    for (int t = 0; t < 2; t++)
        #pragma unroll
        for (int j = 0; j < 8; j++)
            #pragma unroll
            for (int x = 0; x < 4; x++) acc[t][j][x] = 0.f;

    {
        #pragma unroll
        for (int i = 0; i < 4; i++) {
            int mat = i >> 1;
            int r = ((i & 1) << 6) | lrow;
            CP_ASYNC16(sbase + mat * MATB + r * ROWB + lseg * 16,
                       gsrc[mat] + (size_t)r * DD + lseg * 8);
        }
        CP_COMMIT();
    }

    for (int it = 0; it < 32; it++) {
        CP_WAIT0();
        __syncthreads();
        if (it + 1 < 32) {
            int k0 = (it + 1) * 32;
            uint32_t sb = sbase + ((it + 1) & 1) * STAGEB;
            #pragma unroll
            for (int i = 0; i < 4; i++) {
                int mat = i >> 1;
                int r = ((i & 1) << 6) | lrow;
                CP_ASYNC16(sb + mat * MATB + r * ROWB + lseg * 16,
                           gsrc[mat] + (size_t)r * DD + k0 + lseg * 8);
            }
            CP_COMMIT();
        }

        const uint32_t st = sbase + (it & 1) * STAGEB;
        #pragma unroll
        for (int kh = 0; kh < 2; kh++) {
            uint32_t af[2][4], bf[4][4];
            #pragma unroll
            for (int t = 0; t < 2; t++) {
                int row = wm * 32 + t * 16 + (lane & 15);
                LDSM_X4(af[t], st + row * ROWB + (lane >> 4) * 16 + kh * 32);
            }
            #pragma unroll
            for (int jp = 0; jp < 4; jp++) {
                int row = wn * 64 + (2 * jp + (g >> 1)) * 8 + rl;
                LDSM_X4(bf[jp], st + MATB + row * ROWB + (g & 1) * 16 + kh * 32);
            }
            #pragma unroll
            for (int t = 0; t < 2; t++)
                #pragma unroll
                for (int jp = 0; jp < 4; jp++) {
                    MMA_F16(acc[t][2*jp],   af[t], bf[jp]);
                    MMA_F16(acc[t][2*jp+1], af[t], bf[jp]+2);
                }
        }
        __syncthreads();
    }

    const int r0 = lane >> 2, c0 = (lane & 3) * 2;
    #pragma unroll
    for (int t = 0; t < 2; t++) {
        #pragma unroll
        for (int j = 0; j < 8; j++) {
            int o = n0 + wn * 64 + j * 8 + c0;
            #pragma unroll
            for (int h2 = 0; h2 < 2; h2++) {
                int m = m0 + wm * 32 + t * 16 + r0 + h2 * 8;
                float x0 = acc[t][j][2*h2], x1 = acc[t][j][2*h2+1];
                if (o16) {
                    int b = m >> 11, p = m & 2047;
                    int n = o >> 6, hh = o & 63;
                    size_t didx = ((size_t)(b * NH + n) * SS + p) * HD + hh;
                    *(uint32_t*)(o16 + didx) = pack_h2(x0, x1);
                } else {
                    *(float2*)(of + (size_t)m * DD + o) = make_float2(x0, x1);
                }
            }
        }
    }
}

// ---------------------------------------------------------------------------
// GEMM body 64x128 (short-latency O-projection tiles). fp32 row-major out.
// 8 warps: wm = wid&1 (2 x 32 rows), wn = wid>>1 (4 x 32 cols).
// ---------------------------------------------------------------------------
#define MATB_A (64*ROWB)              // 5120
#define STAGE64 (MATB_A + 128*ROWB)   // 15360

__device__ __forceinline__ void gemm64_body(char* smem,
    const __half* __restrict__ A, const __half* __restrict__ B,
    int m0, int n0, float* __restrict__ of)
{
    const int tid = threadIdx.x, lane = tid & 31, wid = tid >> 5;
    const int wm = wid & 1, wn = wid >> 1;
    const uint32_t sbase = smem_u32(smem);
    const int lrow = tid >> 2;
    const int lseg = tid & 3;
    const int g = lane >> 3, rl = lane & 7;

    float acc[2][4][4];
    #pragma unroll
    for (int t = 0; t < 2; t++)
        #pragma unroll
        for (int j = 0; j < 4; j++)
            #pragma unroll
            for (int x = 0; x < 4; x++) acc[t][j][x] = 0.f;

    {
        CP_ASYNC16(sbase + lrow * ROWB + lseg * 16, A + (size_t)lrow * DD + lseg * 8);
        #pragma unroll
        for (int i = 0; i < 2; i++) {
            int r = lrow | (i << 6);
            CP_ASYNC16(sbase + MATB_A + r * ROWB + lseg * 16, B + (size_t)r * DD + lseg * 8);
        }
        CP_COMMIT();
    }

    for (int it = 0; it < 32; it++) {
        CP_WAIT0();
        __syncthreads();
        if (it + 1 < 32) {
            int k0 = (it + 1) * 32;
            uint32_t sb = sbase + ((it + 1) & 1) * STAGE64;
            CP_ASYNC16(sb + lrow * ROWB + lseg * 16, A + (size_t)lrow * DD + k0 + lseg * 8);
            #pragma unroll
            for (int i = 0; i < 2; i++) {
                int r = lrow | (i << 6);
                CP_ASYNC16(sb + MATB_A + r * ROWB + lseg * 16, B + (size_t)r * DD + k0 + lseg * 8);
            }
            CP_COMMIT();
        }

        const uint32_t st = sbase + (it & 1) * STAGE64;
        #pragma unroll
        for (int kh = 0; kh < 2; kh++) {
            uint32_t af[2][4], bf[2][4];
            #pragma unroll
            for (int t = 0; t < 2; t++) {
                int row = wm * 32 + t * 16 + (lane & 15);
                LDSM_X4(af[t], st + row * ROWB + (lane >> 4) * 16 + kh * 32);
            }
            #pragma unroll
            for (int jp = 0; jp < 2; jp++) {
                int row = wn * 32 + (2 * jp + (g >> 1)) * 8 + rl;
                LDSM_X4(bf[jp], st + MATB_A + row * ROWB + (g & 1) * 16 + kh * 32);
            }
            #pragma unroll
            for (int t = 0; t < 2; t++)
                #pragma unroll
                for (int jp = 0; jp < 2; jp++) {
                    MMA_F16(acc[t][2*jp],   af[t], bf[jp]);
                    MMA_F16(acc[t][2*jp+1], af[t], bf[jp]+2);
                }
        }
        __syncthreads();
    }

    const int r0 = lane >> 2, c0 = (lane & 3) * 2;
    #pragma unroll
    for (int t = 0; t < 2; t++) {
        #pragma unroll
        for (int j = 0; j < 4; j++) {
            int o = n0 + wn * 32 + j * 8 + c0;
            #pragma unroll
            for (int h2 = 0; h2 < 2; h2++) {
                int m = m0 + wm * 32 + t * 16 + r0 + h2 * 8;
                *(float2*)(of + (size_t)m * DD + o) =
                    make_float2(acc[t][j][2*h2], acc[t][j][2*h2+1]);
            }
        }
    }
}

// ---------------------------------------------------------------------------
// Attention body (causal), 1-term fp16, exp2 softmax, streaming K/V waits,
// diagonal warp-skip (warps 0-3 skip the fully-masked last k-tile).
// ---------------------------------------------------------------------------
#define AROWB 144
#define AMAT  (64*AROWB)
#define ASTG  (2*AMAT)
#define AQB   (128*AROWB)

__device__ __forceinline__ void attn_body(char* smem,
    const __half* __restrict__ Qg, const __half* __restrict__ Kg,
    const __half* __restrict__ Vg, __half* __restrict__ Og,
    int qb, int n, int b)
{
    const uint32_t sb = smem_u32(smem);
    const int tid = threadIdx.x, lane = tid & 31, wid = tid >> 5;
    const int q0 = qb * 128;
    const size_t base = (size_t)(b * NH + n) * SS * HD;
    const int nt = 2 * qb + 2;
    const uint32_t ST0 = sb + AQB;
    const int ntc = n >> 1;

    auto wait_kv = [&](int j) {
        wait_flag(1 * 256 + (b * 16 + j) * 8 + ntc);
        wait_flag(2 * 256 + (b * 16 + j) * 8 + ntc);
    };

    auto load_tile = [&](int t) {
        uint32_t stb = ST0 + (uint32_t)(t & 1) * ASTG;
        int key0 = t * 64;
        const __half* ms[2] = { Kg + base + (size_t)key0 * HD, Vg + base + (size_t)key0 * HD };
        #pragma unroll
        for (int mt = 0; mt < 2; mt++) {
            #pragma unroll
            for (int u = 0; u < 2; u++) {
                int idx = tid + u * 256;
                int row = idx >> 3, seg = idx & 7;
                CP_ASYNC16(stb + mt * AMAT + row * AROWB + seg * 16,
                           ms[mt] + (size_t)row * HD + seg * 8);
            }
        }
    };

    if (tid == 0) {
        wait_flag(0 * 256 + (b * 16 + qb) * 8 + ntc);
        wait_kv(0);
    }
    __syncthreads();

    {
        const __half* qs = Qg + base + (size_t)q0 * HD;
        #pragma unroll
        for (int u = 0; u < 4; u++) {
            int idx = tid + u * 256;
            int row = idx >> 3, seg = idx & 7;
            CP_ASYNC16(sb + row * AROWB + seg * 16, qs + (size_t)row * HD + seg * 8);
        }
        load_tile(0);
        CP_COMMIT();
        load_tile(1);
        CP_COMMIT();
    }

    CP_WAIT1();
    __syncthreads();

    uint32_t qf[4][4];
    const int qw = wid * 16;
    #pragma unroll
    for (int kh = 0; kh < 4; kh++) {
        uint32_t a = sb + (qw + (lane & 15)) * AROWB + kh * 32 + (lane >> 4) * 16;
        LDSM_X4(qf[kh], a);
    }

    float m0r = -1e30f, m1r = -1e30f, l0r = 0.f, l1r = 0.f;
    float O[8][4];
    #pragma unroll
    for (int j = 0; j < 8; j++)
        #pragma unroll
        for (int x = 0; x < 4; x++) O[j][x] = 0.f;

    const int row0 = q0 + qw + (lane >> 2);
    const int cl = (lane & 3) * 2;

    for (int it = 0; it < nt; it++) {
        const uint32_t stb = ST0 + (uint32_t)(it & 1) * ASTG;
        // warps 0-3 (rows q0..q0+63) fully masked vs keys [q0+64, q0+128)
        const bool active = (wid >= 4) || (it != nt - 1);

        if (active) {
            float S[8][4];
            #pragma unroll
            for (int j = 0; j < 8; j++)
                #pragma unroll
                for (int x = 0; x < 4; x++) S[j][x] = 0.f;

            #pragma unroll
            for (int kh = 0; kh < 4; kh++) {
                uint32_t kb[4][4];
                const int g = lane >> 3, r = lane & 7;
                #pragma unroll
                for (int jp = 0; jp < 4; jp++) {
                    uint32_t a = stb + (uint32_t)(((jp * 2 + (g >> 1)) * 8 + r) * AROWB + (g & 1) * 16 + kh * 32);
                    LDSM_X4(kb[jp], a);
                }
                #pragma unroll
                for (int jp = 0; jp < 4; jp++) {
                    MMA_F16(S[2*jp],   qf[kh], kb[jp]);
                    MMA_F16(S[2*jp+1], qf[kh], kb[jp]+2);
                }
            }

            if (it >= nt - 2) {
                const int kbase = it * 64 + cl;
                #pragma unroll
                for (int j = 0; j < 8; j++) {
                    int c = kbase + j * 8;
                    if (c     > row0)     S[j][0] = -1e30f;
                    if (c + 1 > row0)     S[j][1] = -1e30f;
                    if (c     > row0 + 8) S[j][2] = -1e30f;
                    if (c + 1 > row0 + 8) S[j][3] = -1e30f;
                }
            }

            float mn0 = m0r, mn1 = m1r;
            #pragma unroll
            for (int j = 0; j < 8; j++) {
                mn0 = fmaxf(mn0, fmaxf(S[j][0], S[j][1]));
                mn1 = fmaxf(mn1, fmaxf(S[j][2], S[j][3]));
            }
            mn0 = fmaxf(mn0, __shfl_xor_sync(0xffffffffu, mn0, 1));
            mn0 = fmaxf(mn0, __shfl_xor_sync(0xffffffffu, mn0, 2));
            mn1 = fmaxf(mn1, __shfl_xor_sync(0xffffffffu, mn1, 1));
            mn1 = fmaxf(mn1, __shfl_xor_sync(0xffffffffu, mn1, 2));

            float c0 = ex2f(m0r - mn0), c1 = ex2f(m1r - mn1);
            l0r *= c0; l1r *= c1;
            #pragma unroll
            for (int j = 0; j < 8; j++) {
                O[j][0] *= c0; O[j][1] *= c0; O[j][2] *= c1; O[j][3] *= c1;
            }
            m0r = mn0; m1r = mn1;

            uint32_t ph[4][4];
            float s0 = 0.f, s1 = 0.f;
            #pragma unroll
            for (int j = 0; j < 8; j++) {
                float p0 = ex2f(S[j][0] - mn0), p1 = ex2f(S[j][1] - mn0);
                float p2 = ex2f(S[j][2] - mn1), p3 = ex2f(S[j][3] - mn1);
                s0 += p0 + p1; s1 += p2 + p3;
                int kk = j >> 1, i0 = (j & 1) * 2;
                ph[kk][i0]   = pack_h2(p0, p1);
                ph[kk][i0+1] = pack_h2(p2, p3);
            }
            s0 += __shfl_xor_sync(0xffffffffu, s0, 1);
            s0 += __shfl_xor_sync(0xffffffffu, s0, 2);
            s1 += __shfl_xor_sync(0xffffffffu, s1, 1);
            s1 += __shfl_xor_sync(0xffffffffu, s1, 2);
            l0r += s0; l1r += s1;

            {
                const int g = lane >> 3, r = lane & 7;
                #pragma unroll
                for (int kk = 0; kk < 4; kk++) {
                    #pragma unroll
                    for (int jn = 0; jn < 4; jn++) {
                        uint32_t vb[4];
                        uint32_t a = stb + AMAT
                            + (uint32_t)((kk * 16 + ((g & 1) << 3) + r) * AROWB + (2 * jn + (g >> 1)) * 16);
                        LDSM_X4T(vb, a);
                        MMA_F16(O[2*jn],   ph[kk], vb);
                        MMA_F16(O[2*jn+1], ph[kk], vb+2);
                    }
                }
            }
        }

        __syncthreads();
        int nx = it + 2;
        if (nx < nt) {
            if (tid == 0) wait_kv(nx >> 1);
            __syncthreads();
            load_tile(nx);
            CP_COMMIT();
        }
        if (it + 1 < nt) {
            if (nx < nt) CP_WAIT1(); else CP_WAIT0();
            __syncthreads();
        }
    }

    float inv0 = 1.f / l0r, inv1 = 1.f / l1r;
    size_t orow0 = ((size_t)(b * SS + row0)) * DD + n * HD;
    size_t orow1 = orow0 + (size_t)8 * DD;
    #pragma unroll
    for (int nb = 0; nb < 8; nb++) {
        int d = nb * 8 + cl;
        *(uint32_t*)(Og + orow0 + d) = pack_h2(O[nb][0] * inv0, O[nb][1] * inv0);
        *(uint32_t*)(Og + orow1 + d) = pack_h2(O[nb][2] * inv1, O[nb][3] * inv1);
    }
}

// ---------------------------------------------------------------------------
// Fused dataflow worker, grid = 1792.
// ids [0,256)    : Q projection tiles, qb descending
// ids [256,768)  : K/V projection tiles, key rows j ascending
// ids [768,1280) : attention blocks, qb descending
// ids [1280,1792): O-projection 64x128 tiles, qb ascending
// ---------------------------------------------------------------------------
#define WSMEM (AQB + 2*ASTG)   // 55296 >= gemm bodies' needs

__global__ __launch_bounds__(256, 2) void worker(
    const __half* __restrict__ a16,
    const __half* __restrict__ wq, const __half* __restrict__ wk,
    const __half* __restrict__ wv, const __half* __restrict__ wo,
    __half* __restrict__ q16, __half* __restrict__ k16, __half* __restrict__ v16,
    __half* __restrict__ a216, float* __restrict__ out)
{
    extern __shared__ char smem[];
    const int id = blockIdx.x;
    const int tid = threadIdx.x;

    if (id < 768) {
        // ---- projection tile (criticality-ordered)
        int z, mt, ntl;
        if (id < 256) {
            int r = id >> 3;
            int qb = 15 - (r >> 1);
            int b = r & 1;
            mt = b * 16 + qb;
            z = 0;
            ntl = id & 7;
        } else {
            int u = id - 256;
            int j = u >> 5;
            int rem = u & 31;
            z = 1 + (rem >> 4);
            int sub = rem & 15;
            int b = sub >> 3;
            ntl = sub & 7;
            mt = b * 16 + j;
        }
        const __half* B = (z == 0) ? wq : (z == 1) ? wk : wv;
        __half* o16 = (z == 0) ? q16 : (z == 1) ? k16 : v16;
        gemm_body(smem, a16 + (size_t)mt * 128 * DD, B + (size_t)ntl * 128 * DD,
                  mt * 128, ntl * 128, o16, nullptr);
        __syncthreads();
        __threadfence();
        if (tid == 0) atomicExch(&g_flags[z * 256 + mt * 8 + ntl], 1);
    } else if (id < 1280) {
        // ---- attention block: qb descending
        int a = id - 768;
        int qb = 15 - (a >> 5);
        int rem = a & 31;
        int b = rem >> 4, n = rem & 15;
        attn_body(smem, q16, k16, v16, a216, qb, n, b);
        __syncthreads();
        __threadfence();
        if (tid == 0) atomicExch(&g_flags[768 + (b * 16 + qb) * 16 + n], 1);
    } else {
        // ---- O-projection 64-row tile: ascending qb (dep readiness order)
        int u = id - 1280;                // 0..511
        int qb = u >> 5;
        int rem = u & 31;
        int b = rem >> 4;
        int half = (rem >> 3) & 1;
        int ntl = rem & 7;
        int m0 = b * 2048 + qb * 128 + half * 64;
        if (tid == 0) {
            for (int n = 0; n < 16; n++)
                wait_flag(768 + (b * 16 + qb) * 16 + n);
            __threadfence();
        }
        __syncthreads();
        gemm64_body(smem, a216 + (size_t)m0 * DD, wo + (size_t)ntl * 128 * DD,
                    m0, ntl * 128, out);
    }
}

// ---------------------------------------------------------------------------
extern "C" void kernel_launch(void* const* d_in, const int* in_sizes, int n_in,
                              void* d_out, int out_size)
{
    const float* residual = (const float*)d_in[0];
    const float* W_Q = (const float*)d_in[1];
    const float* W_K = (const float*)d_in[2];
    const float* W_V = (const float*)d_in[3];
    const float* W_O = (const float*)d_in[4];
    float* out = (float*)d_out;

    __half *a16, *a216, *wq, *wk, *wv, *wo, *q16, *k16, *v16;
    cudaGetSymbolAddress((void**)&a16,  g_A16);
    cudaGetSymbolAddress((void**)&a216, g_A216);
    cudaGetSymbolAddress((void**)&wq,   g_WQ16);
    cudaGetSymbolAddress((void**)&wk,   g_WK16);
    cudaGetSymbolAddress((void**)&wv,   g_WV16);
    cudaGetSymbolAddress((void**)&wo,   g_WO16);
    cudaGetSymbolAddress((void**)&q16,  g_Q16);
    cudaGetSymbolAddress((void**)&k16,  g_K16);
    cudaGetSymbolAddress((void**)&v16,  g_V16);

    cudaFuncSetAttribute(worker, cudaFuncAttributeMaxDynamicSharedMemorySize, WSMEM);

    // prep + flag reset (ordering with worker guaranteed by stream order)
    prep_all<<<4608, 256>>>(residual, W_Q, W_K, W_V, W_O);

    // fused QKV -> attention -> O-projection dataflow kernel
    worker<<<1792, 256, WSMEM>>>(a16, wq, wk, wv, wo, q16, k16, v16, a216, out);
}

// round 15
// speedup vs baseline: 1.0433x; 1.0433x over previous
#include <cuda_runtime.h>
#include <cuda_bf16.h>
#include <cuda_fp16.h>
#include <cstdint>
#include <math.h>

// Problem constants
#define BB 2
#define SS 2048
#define DD 1024
#define NH 16
#define HD 64
#define MM (BB*SS)      // 4096
#define QSCALE 0.18033688011112042f   // 0.125 * log2(e)

// ---------------------------------------------------------------------------
// Scratch (device globals)
// ---------------------------------------------------------------------------
__device__ __align__(16) __half g_A16[MM*DD];       // residual fp16
__device__ __align__(16) __half g_A216[MM*DD];      // attn out fp16
__device__ __align__(16) __half g_WQ16[DD*DD];      // pre-scaled by QSCALE
__device__ __align__(16) __half g_WK16[DD*DD];
__device__ __align__(16) __half g_WV16[DD*DD];
__device__ __align__(16) __half g_WO16[DD*DD];      // transposed W_O
__device__ __align__(16) __half g_Q16[BB*NH*SS*HD];
__device__ __align__(16) __half g_K16[BB*NH*SS*HD];
__device__ __align__(16) __half g_V16[BB*NH*SS*HD];
// dataflow flags: [0,768) qkv tiles (z*256+mt*8+ntl); [768,1280) attn ((b*16+qb)*16+n)
__device__ int g_flags[1280];

// ---------------------------------------------------------------------------
// helpers
// ---------------------------------------------------------------------------
__device__ __forceinline__ uint32_t smem_u32(const void* p) {
    uint32_t a;
    asm("{ .reg .u64 t; cvta.to.shared.u64 t, %1; cvt.u32.u64 %0, t; }" : "=r"(a) : "l"(p));
    return a;
}
#define LDSM_X4(r, a) asm volatile("ldmatrix.sync.aligned.m8n8.x4.shared.b16 {%0,%1,%2,%3}, [%4];" \
  : "=r"((r)[0]),"=r"((r)[1]),"=r"((r)[2]),"=r"((r)[3]) : "r"(a))
#define LDSM_X4T(r, a) asm volatile("ldmatrix.sync.aligned.m8n8.x4.trans.shared.b16 {%0,%1,%2,%3}, [%4];" \
  : "=r"((r)[0]),"=r"((r)[1]),"=r"((r)[2]),"=r"((r)[3]) : "r"(a))
#define MMA_F16(d, a, b) asm volatile( \
  "mma.sync.aligned.m16n8k16.row.col.f32.f16.f16.f32 {%0,%1,%2,%3},{%4,%5,%6,%7},{%8,%9},{%0,%1,%2,%3};" \
  : "+f"((d)[0]), "+f"((d)[1]), "+f"((d)[2]), "+f"((d)[3]) \
  : "r"((a)[0]),"r"((a)[1]),"r"((a)[2]),"r"((a)[3]), "r"((b)[0]),"r"((b)[1]))
#define CP_ASYNC16(dst, src) asm volatile("cp.async.cg.shared.global [%0], [%1], 16;" :: "r"(dst), "l"(src))
#define CP_COMMIT() asm volatile("cp.async.commit_group;" ::: "memory")
#define CP_WAIT0()  asm volatile("cp.async.wait_group 0;" ::: "memory")
#define CP_WAIT1()  asm volatile("cp.async.wait_group 1;" ::: "memory")

__device__ __forceinline__ float ex2f(float x) {
    float y; asm("ex2.approx.ftz.f32 %0, %1;" : "=f"(y) : "f"(x)); return y;
}
__device__ __forceinline__ uint32_t pack_h2(float a, float b) {
    uint32_t u;
    asm("{ .reg .f16 lo, hi; cvt.rn.f16.f32 lo, %1; cvt.rn.f16.f32 hi, %2; mov.b32 %0, {lo, hi}; }"
        : "=r"(u) : "f"(a), "f"(b));
    return u;
}
__device__ __forceinline__ void wait_flag(int i) {
    volatile int* f = (volatile int*)&g_flags[i];
    while (*f == 0) { __nanosleep(64); }
}

// ---------------------------------------------------------------------------
// Fused prep + flag reset (one launch, runs before the worker kernel).
// ---------------------------------------------------------------------------
__global__ __launch_bounds__(256) void prep_all(
    const float* __restrict__ residual, const float* __restrict__ W_Q,
    const float* __restrict__ W_K, const float* __restrict__ W_V,
    const float* __restrict__ W_O)
{
    int blk = blockIdx.x;
    if (blk == 0) {
        for (int i = threadIdx.x; i < 1280; i += 256) g_flags[i] = 0;
    }
    if (blk < 3584) {
        const float* src;
        __half* dst;
        float sc = 1.0f;
        int base;
        if (blk < 2048)      { src = residual; dst = g_A16;  base = blk; }
        else if (blk < 2560) { src = W_Q; dst = g_WQ16; base = blk - 2048; sc = QSCALE; }
        else if (blk < 3072) { src = W_K; dst = g_WK16; base = blk - 2560; }
        else                 { src = W_V; dst = g_WV16; base = blk - 3072; }
        int idx = base * 256 + threadIdx.x;
        const float4* s = (const float4*)src + (size_t)idx * 2;
        float4 a0 = s[0], a1 = s[1];
        uint32_t o[4];
        o[0] = pack_h2(a0.x * sc, a0.y * sc);
        o[1] = pack_h2(a0.z * sc, a0.w * sc);
        o[2] = pack_h2(a1.x * sc, a1.y * sc);
        o[3] = pack_h2(a1.z * sc, a1.w * sc);
        ((uint4*)dst)[idx] = *(uint4*)o;
    } else {
        __shared__ float t[32][33];
        int tile = blk - 3584;
        int bx = (tile & 31) * 32;
        int by = (tile >> 5) * 32;
        int tx = threadIdx.x & 31, ty = threadIdx.x >> 5;
        #pragma unroll
        for (int i = 0; i < 4; i++)
            t[ty + 8*i][tx] = W_O[(size_t)(by + ty + 8*i) * DD + bx + tx];
        __syncthreads();
        #pragma unroll
        for (int i = 0; i < 4; i++) {
            float v = t[tx][ty + 8*i];
            g_WO16[(size_t)(bx + ty + 8*i) * DD + by + tx] = __float2half_rn(v);
        }
    }
}

// ---------------------------------------------------------------------------
// GEMM body 128x128: C tile = A[128xK] * B[128xK]^T, fp16 in, fp32 acc.
// o16 != nullptr: scatter fp16 to [b,n,p,h]; else fp32 row-major to of.
// fbase >= 0: streaming K-dependency — before loading A columns [k0,k0+64)
// (one attention head), wait on g_flags[fbase + k0/64].
// ---------------------------------------------------------------------------
#define ROWB 80
#define MATB (128*ROWB)
#define STAGEB (2*MATB)

__device__ __forceinline__ void gemm_body(char* smem,
    const __half* __restrict__ A, const __half* __restrict__ B,
    int m0, int n0, __half* __restrict__ o16, float* __restrict__ of,
    int fbase)
{
    const int tid = threadIdx.x, lane = tid & 31, wid = tid >> 5;
    const int wm = wid & 3, wn = wid >> 2;
    const __half* gsrc[2] = { A, B };

    const uint32_t sbase = smem_u32(smem);
    const int lrow = tid >> 2;
    const int lseg = tid & 3;
    const int g = lane >> 3, rl = lane & 7;

    float acc[2][8][4];
    #pragma unroll
    for (int t = 0; t < 2; t++)
        #pragma unroll
        for (int j = 0; j < 8; j++)
            #pragma unroll
            for (int x = 0; x < 4; x++) acc[t][j][x] = 0.f;

    {
        if (fbase >= 0) {
            if (tid == 0) wait_flag(fbase);    // head 0 ready
            __syncthreads();
        }
        #pragma unroll
        for (int i = 0; i < 4; i++) {
            int mat = i >> 1;
            int r = ((i & 1) << 6) | lrow;
            CP_ASYNC16(sbase + mat * MATB + r * ROWB + lseg * 16,
                       gsrc[mat] + (size_t)r * DD + lseg * 8);
        }
        CP_COMMIT();
    }

    for (int it = 0; it < 32; it++) {
        CP_WAIT0();
        __syncthreads();
        if (it + 1 < 32) {
            // streaming dependency: next chunk k0=(it+1)*32 belongs to head (it+1)/2
            if (fbase >= 0 && (((it + 1) & 1) == 0)) {
                if (tid == 0) wait_flag(fbase + ((it + 1) >> 1));
                __syncthreads();
            }
            int k0 = (it + 1) * 32;
            uint32_t sb = sbase + ((it + 1) & 1) * STAGEB;
            #pragma unroll
            for (int i = 0; i < 4; i++) {
                int mat = i >> 1;
                int r = ((i & 1) << 6) | lrow;
                CP_ASYNC16(sb + mat * MATB + r * ROWB + lseg * 16,
                           gsrc[mat] + (size_t)r * DD + k0 + lseg * 8);
            }
            CP_COMMIT();
        }

        const uint32_t st = sbase + (it & 1) * STAGEB;
        #pragma unroll
        for (int kh = 0; kh < 2; kh++) {
            uint32_t af[2][4], bf[4][4];
            #pragma unroll
            for (int t = 0; t < 2; t++) {
                int row = wm * 32 + t * 16 + (lane & 15);
                LDSM_X4(af[t], st + row * ROWB + (lane >> 4) * 16 + kh * 32);
            }
            #pragma unroll
            for (int jp = 0; jp < 4; jp++) {
                int row = wn * 64 + (2 * jp + (g >> 1)) * 8 + rl;
                LDSM_X4(bf[jp], st + MATB + row * ROWB + (g & 1) * 16 + kh * 32);
            }
            #pragma unroll
            for (int t = 0; t < 2; t++)
                #pragma unroll
                for (int jp = 0; jp < 4; jp++) {
                    MMA_F16(acc[t][2*jp],   af[t], bf[jp]);
                    MMA_F16(acc[t][2*jp+1], af[t], bf[jp]+2);
                }
        }
        __syncthreads();
    }

    const int r0 = lane >> 2, c0 = (lane & 3) * 2;
    #pragma unroll
    for (int t = 0; t < 2; t++) {
        #pragma unroll
        for (int j = 0; j < 8; j++) {
            int o = n0 + wn * 64 + j * 8 + c0;
            #pragma unroll
            for (int h2 = 0; h2 < 2; h2++) {
                int m = m0 + wm * 32 + t * 16 + r0 + h2 * 8;
                float x0 = acc[t][j][2*h2], x1 = acc[t][j][2*h2+1];
                if (o16) {
                    int b = m >> 11, p = m & 2047;
                    int n = o >> 6, hh = o & 63;
                    size_t didx = ((size_t)(b * NH + n) * SS + p) * HD + hh;
                    *(uint32_t*)(o16 + didx) = pack_h2(x0, x1);
                } else {
                    *(float2*)(of + (size_t)m * DD + o) = make_float2(x0, x1);
                }
            }
        }
    }
}

// ---------------------------------------------------------------------------
// Attention body (causal), 1-term fp16, exp2 softmax, streaming K/V waits,
// diagonal warp-skip (warps 0-3 skip the fully-masked last k-tile; exact).
// ---------------------------------------------------------------------------
#define AROWB 144
#define AMAT  (64*AROWB)
#define ASTG  (2*AMAT)
#define AQB   (128*AROWB)

__device__ __forceinline__ void attn_body(char* smem,
    const __half* __restrict__ Qg, const __half* __restrict__ Kg,
    const __half* __restrict__ Vg, __half* __restrict__ Og,
    int qb, int n, int b)
{
    const uint32_t sb = smem_u32(smem);
    const int tid = threadIdx.x, lane = tid & 31, wid = tid >> 5;
    const int q0 = qb * 128;
    const size_t base = (size_t)(b * NH + n) * SS * HD;
    const int nt = 2 * qb + 2;
    const uint32_t ST0 = sb + AQB;
    const int ntc = n >> 1;

    auto wait_kv = [&](int j) {
        wait_flag(1 * 256 + (b * 16 + j) * 8 + ntc);
        wait_flag(2 * 256 + (b * 16 + j) * 8 + ntc);
    };

    auto load_tile = [&](int t) {
        uint32_t stb = ST0 + (uint32_t)(t & 1) * ASTG;
        int key0 = t * 64;
        const __half* ms[2] = { Kg + base + (size_t)key0 * HD, Vg + base + (size_t)key0 * HD };
        #pragma unroll
        for (int mt = 0; mt < 2; mt++) {
            #pragma unroll
            for (int u = 0; u < 2; u++) {
                int idx = tid + u * 256;
                int row = idx >> 3, seg = idx & 7;
                CP_ASYNC16(stb + mt * AMAT + row * AROWB + seg * 16,
                           ms[mt] + (size_t)row * HD + seg * 8);
            }
        }
    };

    if (tid == 0) {
        wait_flag(0 * 256 + (b * 16 + qb) * 8 + ntc);
        wait_kv(0);
    }
    __syncthreads();

    {
        const __half* qs = Qg + base + (size_t)q0 * HD;
        #pragma unroll
        for (int u = 0; u < 4; u++) {
            int idx = tid + u * 256;
            int row = idx >> 3, seg = idx & 7;
            CP_ASYNC16(sb + row * AROWB + seg * 16, qs + (size_t)row * HD + seg * 8);
        }
        load_tile(0);
        CP_COMMIT();
        load_tile(1);
        CP_COMMIT();
    }

    CP_WAIT1();
    __syncthreads();

    uint32_t qf[4][4];
    const int qw = wid * 16;
    #pragma unroll
    for (int kh = 0; kh < 4; kh++) {
        uint32_t a = sb + (qw + (lane & 15)) * AROWB + kh * 32 + (lane >> 4) * 16;
        LDSM_X4(qf[kh], a);
    }

    float m0r = -1e30f, m1r = -1e30f, l0r = 0.f, l1r = 0.f;
    float O[8][4];
    #pragma unroll
    for (int j = 0; j < 8; j++)
        #pragma unroll
        for (int x = 0; x < 4; x++) O[j][x] = 0.f;

    const int row0 = q0 + qw + (lane >> 2);
    const int cl = (lane & 3) * 2;

    for (int it = 0; it < nt; it++) {
        const uint32_t stb = ST0 + (uint32_t)(it & 1) * ASTG;
        // warps 0-3 (rows q0..q0+63) fully masked vs keys [q0+64, q0+128)
        const bool active = (wid >= 4) || (it != nt - 1);

        if (active) {
            float S[8][4];
            #pragma unroll
            for (int j = 0; j < 8; j++)
                #pragma unroll
                for (int x = 0; x < 4; x++) S[j][x] = 0.f;

            #pragma unroll
            for (int kh = 0; kh < 4; kh++) {
                uint32_t kb[4][4];
                const int g = lane >> 3, r = lane & 7;
                #pragma unroll
                for (int jp = 0; jp < 4; jp++) {
                    uint32_t a = stb + (uint32_t)(((jp * 2 + (g >> 1)) * 8 + r) * AROWB + (g & 1) * 16 + kh * 32);
                    LDSM_X4(kb[jp], a);
                }
                #pragma unroll
                for (int jp = 0; jp < 4; jp++) {
                    MMA_F16(S[2*jp],   qf[kh], kb[jp]);
                    MMA_F16(S[2*jp+1], qf[kh], kb[jp]+2);
                }
            }

            if (it >= nt - 2) {
                const int kbase = it * 64 + cl;
                #pragma unroll
                for (int j = 0; j < 8; j++) {
                    int c = kbase + j * 8;
                    if (c     > row0)     S[j][0] = -1e30f;
                    if (c + 1 > row0)     S[j][1] = -1e30f;
                    if (c     > row0 + 8) S[j][2] = -1e30f;
                    if (c + 1 > row0 + 8) S[j][3] = -1e30f;
                }
            }

            float mn0 = m0r, mn1 = m1r;
            #pragma unroll
            for (int j = 0; j < 8; j++) {
                mn0 = fmaxf(mn0, fmaxf(S[j][0], S[j][1]));
                mn1 = fmaxf(mn1, fmaxf(S[j][2], S[j][3]));
            }
            mn0 = fmaxf(mn0, __shfl_xor_sync(0xffffffffu, mn0, 1));
            mn0 = fmaxf(mn0, __shfl_xor_sync(0xffffffffu, mn0, 2));
            mn1 = fmaxf(mn1, __shfl_xor_sync(0xffffffffu, mn1, 1));
            mn1 = fmaxf(mn1, __shfl_xor_sync(0xffffffffu, mn1, 2));

            float c0 = ex2f(m0r - mn0), c1 = ex2f(m1r - mn1);
            l0r *= c0; l1r *= c1;
            #pragma unroll
            for (int j = 0; j < 8; j++) {
                O[j][0] *= c0; O[j][1] *= c0; O[j][2] *= c1; O[j][3] *= c1;
            }
            m0r = mn0; m1r = mn1;

            uint32_t ph[4][4];
            float s0 = 0.f, s1 = 0.f;
            #pragma unroll
            for (int j = 0; j < 8; j++) {
                float p0 = ex2f(S[j][0] - mn0), p1 = ex2f(S[j][1] - mn0);
                float p2 = ex2f(S[j][2] - mn1), p3 = ex2f(S[j][3] - mn1);
                s0 += p0 + p1; s1 += p2 + p3;
                int kk = j >> 1, i0 = (j & 1) * 2;
                ph[kk][i0]   = pack_h2(p0, p1);
                ph[kk][i0+1] = pack_h2(p2, p3);
            }
            s0 += __shfl_xor_sync(0xffffffffu, s0, 1);
            s0 += __shfl_xor_sync(0xffffffffu, s0, 2);
            s1 += __shfl_xor_sync(0xffffffffu, s1, 1);
            s1 += __shfl_xor_sync(0xffffffffu, s1, 2);
            l0r += s0; l1r += s1;

            {
                const int g = lane >> 3, r = lane & 7;
                #pragma unroll
                for (int kk = 0; kk < 4; kk++) {
                    #pragma unroll
                    for (int jn = 0; jn < 4; jn++) {
                        uint32_t vb[4];
                        uint32_t a = stb + AMAT
                            + (uint32_t)((kk * 16 + ((g & 1) << 3) + r) * AROWB + (2 * jn + (g >> 1)) * 16);
                        LDSM_X4T(vb, a);
                        MMA_F16(O[2*jn],   ph[kk], vb);
                        MMA_F16(O[2*jn+1], ph[kk], vb+2);
                    }
                }
            }
        }

        __syncthreads();
        int nx = it + 2;
        if (nx < nt) {
            if (tid == 0) wait_kv(nx >> 1);
            __syncthreads();
            load_tile(nx);
            CP_COMMIT();
        }
        if (it + 1 < nt) {
            if (nx < nt) CP_WAIT1(); else CP_WAIT0();
            __syncthreads();
        }
    }

    float inv0 = 1.f / l0r, inv1 = 1.f / l1r;
    size_t orow0 = ((size_t)(b * SS + row0)) * DD + n * HD;
    size_t orow1 = orow0 + (size_t)8 * DD;
    #pragma unroll
    for (int nb = 0; nb < 8; nb++) {
        int d = nb * 8 + cl;
        *(uint32_t*)(Og + orow0 + d) = pack_h2(O[nb][0] * inv0, O[nb][1] * inv0);
        *(uint32_t*)(Og + orow1 + d) = pack_h2(O[nb][2] * inv1, O[nb][3] * inv1);
    }
}

// ---------------------------------------------------------------------------
// Fused dataflow worker, grid = 1536.
// ids [0,256)    : Q projection tiles, qb descending
// ids [256,768)  : K/V projection tiles, key rows j ascending
// ids [768,1280) : attention blocks, qb descending
// ids [1280,1536): O-projection 128x128 tiles with STREAMING per-head waits
// ---------------------------------------------------------------------------
#define WSMEM (AQB + 2*ASTG)   // 55296 >= gemm's 40960

__global__ __launch_bounds__(256, 2) void worker(
    const __half* __restrict__ a16,
    const __half* __restrict__ wq, const __half* __restrict__ wk,
    const __half* __restrict__ wv, const __half* __restrict__ wo,
    __half* __restrict__ q16, __half* __restrict__ k16, __half* __restrict__ v16,
    __half* __restrict__ a216, float* __restrict__ out)
{
    extern __shared__ char smem[];
    const int id = blockIdx.x;
    const int tid = threadIdx.x;

    if (id < 768) {
        // ---- projection tile (criticality-ordered)
        int z, mt, ntl;
        if (id < 256) {
            int r = id >> 3;
            int qb = 15 - (r >> 1);
            int b = r & 1;
            mt = b * 16 + qb;
            z = 0;
            ntl = id & 7;
        } else {
            int u = id - 256;
            int j = u >> 5;
            int rem = u & 31;
            z = 1 + (rem >> 4);
            int sub = rem & 15;
            int b = sub >> 3;
            ntl = sub & 7;
            mt = b * 16 + j;
        }
        const __half* B = (z == 0) ? wq : (z == 1) ? wk : wv;
        __half* o16 = (z == 0) ? q16 : (z == 1) ? k16 : v16;
        gemm_body(smem, a16 + (size_t)mt * 128 * DD, B + (size_t)ntl * 128 * DD,
                  mt * 128, ntl * 128, o16, nullptr, -1);
        __syncthreads();
        __threadfence();
        if (tid == 0) atomicExch(&g_flags[z * 256 + mt * 8 + ntl], 1);
    } else if (id < 1280) {
        // ---- attention block: qb descending
        int a = id - 768;
        int qb = 15 - (a >> 5);
        int rem = a & 31;
        int b = rem >> 4, n = rem & 15;
        attn_body(smem, q16, k16, v16, a216, qb, n, b);
        __syncthreads();
        __threadfence();
        if (tid == 0) atomicExch(&g_flags[768 + (b * 16 + qb) * 16 + n], 1);
    } else {
        // ---- O-projection tile with streaming per-head dependency
        int o = id - 1280;
        int qb2 = o >> 3;                 // qb*2 + b
        int ntl = o & 7;
        int qb = qb2 >> 1, b = qb2 & 1;
        int mt = b * 16 + qb;
        int fbase = 768 + (b * 16 + qb) * 16;
        gemm_body(smem, a216 + (size_t)mt * 128 * DD, wo + (size_t)ntl * 128 * DD,
                  mt * 128, ntl * 128, nullptr, out, fbase);
    }
}

// ---------------------------------------------------------------------------
extern "C" void kernel_launch(void* const* d_in, const int* in_sizes, int n_in,
                              void* d_out, int out_size)
{
    const float* residual = (const float*)d_in[0];
    const float* W_Q = (const float*)d_in[1];
    const float* W_K = (const float*)d_in[2];
    const float* W_V = (const float*)d_in[3];
    const float* W_O = (const float*)d_in[4];
    float* out = (float*)d_out;

    __half *a16, *a216, *wq, *wk, *wv, *wo, *q16, *k16, *v16;
    cudaGetSymbolAddress((void**)&a16,  g_A16);
    cudaGetSymbolAddress((void**)&a216, g_A216);
    cudaGetSymbolAddress((void**)&wq,   g_WQ16);
    cudaGetSymbolAddress((void**)&wk,   g_WK16);
    cudaGetSymbolAddress((void**)&wv,   g_WV16);
    cudaGetSymbolAddress((void**)&wo,   g_WO16);
    cudaGetSymbolAddress((void**)&q16,  g_Q16);
    cudaGetSymbolAddress((void**)&k16,  g_K16);
    cudaGetSymbolAddress((void**)&v16,  g_V16);

    cudaFuncSetAttribute(worker, cudaFuncAttributeMaxDynamicSharedMemorySize, WSMEM);

    // prep + flag reset (ordering with worker guaranteed by stream order)
    prep_all<<<4608, 256>>>(residual, W_Q, W_K, W_V, W_O);

    // fused QKV -> attention -> O-projection dataflow kernel
    worker<<<1536, 256, WSMEM>>>(a16, wq, wk, wv, wo, q16, k16, v16, a216, out);
}

// round 16
// speedup vs baseline: 1.0499x; 1.0063x over previous
#include <cuda_runtime.h>
#include <cuda_bf16.h>
#include <cuda_fp16.h>
#include <cstdint>
#include <math.h>

// Problem constants
#define BB 2
#define SS 2048
#define DD 1024
#define NH 16
#define HD 64
#define MM (BB*SS)      // 4096
#define QSCALE 0.18033688011112042f   // 0.125 * log2(e)

// ---------------------------------------------------------------------------
// Scratch (device globals)
// ---------------------------------------------------------------------------
__device__ __align__(16) __half g_A16[MM*DD];       // residual fp16
__device__ __align__(16) __half g_A216[MM*DD];      // attn out fp16
__device__ __align__(16) __half g_WQ16[DD*DD];      // pre-scaled by QSCALE
__device__ __align__(16) __half g_WK16[DD*DD];
__device__ __align__(16) __half g_WV16[DD*DD];
__device__ __align__(16) __half g_WO16[DD*DD];      // transposed W_O
__device__ __align__(16) __half g_Q16[BB*NH*SS*HD];
__device__ __align__(16) __half g_K16[BB*NH*SS*HD];
__device__ __align__(16) __half g_V16[BB*NH*SS*HD];
// dataflow flags: [0,768) qkv tiles (z*256+mt*8+ntl); [768,1280) attn ((b*16+qb)*16+n)
__device__ int g_flags[1280];

// ---------------------------------------------------------------------------
// helpers
// ---------------------------------------------------------------------------
__device__ __forceinline__ uint32_t smem_u32(const void* p) {
    uint32_t a;
    asm("{ .reg .u64 t; cvta.to.shared.u64 t, %1; cvt.u32.u64 %0, t; }" : "=r"(a) : "l"(p));
    return a;
}
#define LDSM_X4(r, a) asm volatile("ldmatrix.sync.aligned.m8n8.x4.shared.b16 {%0,%1,%2,%3}, [%4];" \
  : "=r"((r)[0]),"=r"((r)[1]),"=r"((r)[2]),"=r"((r)[3]) : "r"(a))
#define LDSM_X4T(r, a) asm volatile("ldmatrix.sync.aligned.m8n8.x4.trans.shared.b16 {%0,%1,%2,%3}, [%4];" \
  : "=r"((r)[0]),"=r"((r)[1]),"=r"((r)[2]),"=r"((r)[3]) : "r"(a))
#define MMA_F16(d, a, b) asm volatile( \
  "mma.sync.aligned.m16n8k16.row.col.f32.f16.f16.f32 {%0,%1,%2,%3},{%4,%5,%6,%7},{%8,%9},{%0,%1,%2,%3};" \
  : "+f"((d)[0]), "+f"((d)[1]), "+f"((d)[2]), "+f"((d)[3]) \
  : "r"((a)[0]),"r"((a)[1]),"r"((a)[2]),"r"((a)[3]), "r"((b)[0]),"r"((b)[1]))
#define CP_ASYNC16(dst, src) asm volatile("cp.async.cg.shared.global [%0], [%1], 16;" :: "r"(dst), "l"(src))
#define CP_COMMIT() asm volatile("cp.async.commit_group;" ::: "memory")
#define CP_WAIT0()  asm volatile("cp.async.wait_group 0;" ::: "memory")
#define CP_WAIT1()  asm volatile("cp.async.wait_group 1;" ::: "memory")

__device__ __forceinline__ float ex2f(float x) {
    float y; asm("ex2.approx.ftz.f32 %0, %1;" : "=f"(y) : "f"(x)); return y;
}
__device__ __forceinline__ uint32_t pack_h2(float a, float b) {
    uint32_t u;
    asm("{ .reg .f16 lo, hi; cvt.rn.f16.f32 lo, %1; cvt.rn.f16.f32 hi, %2; mov.b32 %0, {lo, hi}; }"
        : "=r"(u) : "f"(a), "f"(b));
    return u;
}
__device__ __forceinline__ void wait_flag(int i) {
    volatile int* f = (volatile int*)&g_flags[i];
    while (*f == 0) { __nanosleep(64); }
}

// ---------------------------------------------------------------------------
// Fused prep + flag reset (one launch, runs before the worker kernel).
// ---------------------------------------------------------------------------
__global__ __launch_bounds__(256) void prep_all(
    const float* __restrict__ residual, const float* __restrict__ W_Q,
    const float* __restrict__ W_K, const float* __restrict__ W_V,
    const float* __restrict__ W_O)
{
    int blk = blockIdx.x;
    if (blk == 0) {
        for (int i = threadIdx.x; i < 1280; i += 256) g_flags[i] = 0;
    }
    if (blk < 3584) {
        const float* src;
        __half* dst;
        float sc = 1.0f;
        int base;
        if (blk < 2048)      { src = residual; dst = g_A16;  base = blk; }
        else if (blk < 2560) { src = W_Q; dst = g_WQ16; base = blk - 2048; sc = QSCALE; }
        else if (blk < 3072) { src = W_K; dst = g_WK16; base = blk - 2560; }
        else                 { src = W_V; dst = g_WV16; base = blk - 3072; }
        int idx = base * 256 + threadIdx.x;
        const float4* s = (const float4*)src + (size_t)idx * 2;
        float4 a0 = s[0], a1 = s[1];
        uint32_t o[4];
        o[0] = pack_h2(a0.x * sc, a0.y * sc);
        o[1] = pack_h2(a0.z * sc, a0.w * sc);
        o[2] = pack_h2(a1.x * sc, a1.y * sc);
        o[3] = pack_h2(a1.z * sc, a1.w * sc);
        ((uint4*)dst)[idx] = *(uint4*)o;
    } else {
        __shared__ float t[32][33];
        int tile = blk - 3584;
        int bx = (tile & 31) * 32;
        int by = (tile >> 5) * 32;
        int tx = threadIdx.x & 31, ty = threadIdx.x >> 5;
        #pragma unroll
        for (int i = 0; i < 4; i++)
            t[ty + 8*i][tx] = W_O[(size_t)(by + ty + 8*i) * DD + bx + tx];
        __syncthreads();
        #pragma unroll
        for (int i = 0; i < 4; i++) {
            float v = t[tx][ty + 8*i];
            g_WO16[(size_t)(bx + ty + 8*i) * DD + by + tx] = __float2half_rn(v);
        }
    }
}

// ---------------------------------------------------------------------------
// GEMM body 128x128, 3-stage cp.async pipeline (2-chunk prefetch lead).
// o16 != nullptr: scatter fp16 to [b,n,p,h]; else fp32 row-major to of.
// fbase >= 0: streaming per-head dependency on A columns.
// ---------------------------------------------------------------------------
#define ROWB 80
#define MATB (128*ROWB)
#define STAGEB (2*MATB)        // 20480

__device__ __forceinline__ void gemm_body(char* smem,
    const __half* __restrict__ A, const __half* __restrict__ B,
    int m0, int n0, __half* __restrict__ o16, float* __restrict__ of,
    int fbase)
{
    const int tid = threadIdx.x, lane = tid & 31, wid = tid >> 5;
    const int wm = wid & 3, wn = wid >> 2;
    const __half* gsrc[2] = { A, B };

    const uint32_t sbase = smem_u32(smem);
    const int lrow = tid >> 2;
    const int lseg = tid & 3;
    const int g = lane >> 3, rl = lane & 7;

    float acc[2][8][4];
    #pragma unroll
    for (int t = 0; t < 2; t++)
        #pragma unroll
        for (int j = 0; j < 8; j++)
            #pragma unroll
            for (int x = 0; x < 4; x++) acc[t][j][x] = 0.f;

    auto issue_stage = [&](int c) {   // chunk c -> stage c%3
        uint32_t sb = sbase + (uint32_t)(c % 3) * STAGEB;
        int k0 = c * 32;
        #pragma unroll
        for (int i = 0; i < 4; i++) {
            int mat = i >> 1;
            int r = ((i & 1) << 6) | lrow;
            CP_ASYNC16(sb + mat * MATB + r * ROWB + lseg * 16,
                       gsrc[mat] + (size_t)r * DD + k0 + lseg * 8);
        }
        CP_COMMIT();
    };

    // prologue: chunks 0 and 1 (both in head 0 for the streaming case)
    if (fbase >= 0) {
        if (tid == 0) wait_flag(fbase);
        __syncthreads();
    }
    issue_stage(0);
    issue_stage(1);

    for (int it = 0; it < 32; it++) {
        if (it < 31) CP_WAIT1(); else CP_WAIT0();
        __syncthreads();                      // stage it ready; prior compute done
        int nx = it + 2;
        if (nx < 32) {
            if (fbase >= 0 && ((nx & 1) == 0)) {
                if (tid == 0) wait_flag(fbase + (nx >> 1));
                __syncthreads();
            }
            issue_stage(nx);
        }

        const uint32_t st = sbase + (uint32_t)(it % 3) * STAGEB;
        #pragma unroll
        for (int kh = 0; kh < 2; kh++) {
            uint32_t af[2][4], bf[4][4];
            #pragma unroll
            for (int t = 0; t < 2; t++) {
                int row = wm * 32 + t * 16 + (lane & 15);
                LDSM_X4(af[t], st + row * ROWB + (lane >> 4) * 16 + kh * 32);
            }
            #pragma unroll
            for (int jp = 0; jp < 4; jp++) {
                int row = wn * 64 + (2 * jp + (g >> 1)) * 8 + rl;
                LDSM_X4(bf[jp], st + MATB + row * ROWB + (g & 1) * 16 + kh * 32);
            }
            #pragma unroll
            for (int t = 0; t < 2; t++)
                #pragma unroll
                for (int jp = 0; jp < 4; jp++) {
                    MMA_F16(acc[t][2*jp],   af[t], bf[jp]);
                    MMA_F16(acc[t][2*jp+1], af[t], bf[jp]+2);
                }
        }
    }

    const int r0 = lane >> 2, c0 = (lane & 3) * 2;
    #pragma unroll
    for (int t = 0; t < 2; t++) {
        #pragma unroll
        for (int j = 0; j < 8; j++) {
            int o = n0 + wn * 64 + j * 8 + c0;
            #pragma unroll
            for (int h2 = 0; h2 < 2; h2++) {
                int m = m0 + wm * 32 + t * 16 + r0 + h2 * 8;
                float x0 = acc[t][j][2*h2], x1 = acc[t][j][2*h2+1];
                if (o16) {
                    int b = m >> 11, p = m & 2047;
                    int n = o >> 6, hh = o & 63;
                    size_t didx = ((size_t)(b * NH + n) * SS + p) * HD + hh;
                    *(uint32_t*)(o16 + didx) = pack_h2(x0, x1);
                } else {
                    *(float2*)(of + (size_t)m * DD + o) = make_float2(x0, x1);
                }
            }
        }
    }
}

// ---------------------------------------------------------------------------
// Attention body (causal), 1-term fp16, exp2 softmax, 3-stage K/V pipeline,
// streaming K/V flag waits, diagonal warp-skip (exact).
// ---------------------------------------------------------------------------
#define AROWB 144
#define AMAT  (64*AROWB)
#define ASTG  (2*AMAT)         // 18432
#define AQB   (128*AROWB)      // 18432

__device__ __forceinline__ void attn_body(char* smem,
    const __half* __restrict__ Qg, const __half* __restrict__ Kg,
    const __half* __restrict__ Vg, __half* __restrict__ Og,
    int qb, int n, int b)
{
    const uint32_t sb = smem_u32(smem);
    const int tid = threadIdx.x, lane = tid & 31, wid = tid >> 5;
    const int q0 = qb * 128;
    const size_t base = (size_t)(b * NH + n) * SS * HD;
    const int nt = 2 * qb + 2;
    const uint32_t ST0 = sb + AQB;
    const int ntc = n >> 1;

    auto wait_kv = [&](int j) {
        wait_flag(1 * 256 + (b * 16 + j) * 8 + ntc);
        wait_flag(2 * 256 + (b * 16 + j) * 8 + ntc);
    };

    auto load_tile = [&](int t) {      // tile t -> stage t%3
        uint32_t stb = ST0 + (uint32_t)(t % 3) * ASTG;
        int key0 = t * 64;
        const __half* ms[2] = { Kg + base + (size_t)key0 * HD, Vg + base + (size_t)key0 * HD };
        #pragma unroll
        for (int mt = 0; mt < 2; mt++) {
            #pragma unroll
            for (int u = 0; u < 2; u++) {
                int idx = tid + u * 256;
                int row = idx >> 3, seg = idx & 7;
                CP_ASYNC16(stb + mt * AMAT + row * AROWB + seg * 16,
                           ms[mt] + (size_t)row * HD + seg * 8);
            }
        }
    };

    if (tid == 0) {
        wait_flag(0 * 256 + (b * 16 + qb) * 8 + ntc);
        wait_kv(0);
    }
    __syncthreads();

    {
        const __half* qs = Qg + base + (size_t)q0 * HD;
        #pragma unroll
        for (int u = 0; u < 4; u++) {
            int idx = tid + u * 256;
            int row = idx >> 3, seg = idx & 7;
            CP_ASYNC16(sb + row * AROWB + seg * 16, qs + (size_t)row * HD + seg * 8);
        }
        load_tile(0);
        CP_COMMIT();       // group0: Q + tile0
        load_tile(1);
        CP_COMMIT();       // group1: tile1
    }

    CP_WAIT1();            // Q + tile0 ready
    __syncthreads();

    uint32_t qf[4][4];
    const int qw = wid * 16;
    #pragma unroll
    for (int kh = 0; kh < 4; kh++) {
        uint32_t a = sb + (qw + (lane & 15)) * AROWB + kh * 32 + (lane >> 4) * 16;
        LDSM_X4(qf[kh], a);
    }

    float m0r = -1e30f, m1r = -1e30f, l0r = 0.f, l1r = 0.f;
    float O[8][4];
    #pragma unroll
    for (int j = 0; j < 8; j++)
        #pragma unroll
        for (int x = 0; x < 4; x++) O[j][x] = 0.f;

    const int row0 = q0 + qw + (lane >> 2);
    const int cl = (lane & 3) * 2;

    for (int it = 0; it < nt; it++) {
        if (it < nt - 1) CP_WAIT1(); else CP_WAIT0();
        __syncthreads();                 // tile it ready; prior compute done
        int nx = it + 2;
        if (nx < nt) {
            if (tid == 0) wait_kv(nx >> 1);
            __syncthreads();
            load_tile(nx);
            CP_COMMIT();
        }

        const uint32_t stb = ST0 + (uint32_t)(it % 3) * ASTG;
        // warps 0-3 (rows q0..q0+63) fully masked vs keys [q0+64, q0+128)
        const bool active = (wid >= 4) || (it != nt - 1);

        if (active) {
            float S[8][4];
            #pragma unroll
            for (int j = 0; j < 8; j++)
                #pragma unroll
                for (int x = 0; x < 4; x++) S[j][x] = 0.f;

            #pragma unroll
            for (int kh = 0; kh < 4; kh++) {
                uint32_t kb[4][4];
                const int g = lane >> 3, r = lane & 7;
                #pragma unroll
                for (int jp = 0; jp < 4; jp++) {
                    uint32_t a = stb + (uint32_t)(((jp * 2 + (g >> 1)) * 8 + r) * AROWB + (g & 1) * 16 + kh * 32);
                    LDSM_X4(kb[jp], a);
                }
                #pragma unroll
                for (int jp = 0; jp < 4; jp++) {
                    MMA_F16(S[2*jp],   qf[kh], kb[jp]);
                    MMA_F16(S[2*jp+1], qf[kh], kb[jp]+2);
                }
            }

            if (it >= nt - 2) {
                const int kbase = it * 64 + cl;
                #pragma unroll
                for (int j = 0; j < 8; j++) {
                    int c = kbase + j * 8;
                    if (c     > row0)     S[j][0] = -1e30f;
                    if (c + 1 > row0)     S[j][1] = -1e30f;
                    if (c     > row0 + 8) S[j][2] = -1e30f;
                    if (c + 1 > row0 + 8) S[j][3] = -1e30f;
                }
            }

            float mn0 = m0r, mn1 = m1r;
            #pragma unroll
            for (int j = 0; j < 8; j++) {
                mn0 = fmaxf(mn0, fmaxf(S[j][0], S[j][1]));
                mn1 = fmaxf(mn1, fmaxf(S[j][2], S[j][3]));
            }
            mn0 = fmaxf(mn0, __shfl_xor_sync(0xffffffffu, mn0, 1));
            mn0 = fmaxf(mn0, __shfl_xor_sync(0xffffffffu, mn0, 2));
            mn1 = fmaxf(mn1, __shfl_xor_sync(0xffffffffu, mn1, 1));
            mn1 = fmaxf(mn1, __shfl_xor_sync(0xffffffffu, mn1, 2));

            float c0 = ex2f(m0r - mn0), c1 = ex2f(m1r - mn1);
            l0r *= c0; l1r *= c1;
            #pragma unroll
            for (int j = 0; j < 8; j++) {
                O[j][0] *= c0; O[j][1] *= c0; O[j][2] *= c1; O[j][3] *= c1;
            }
            m0r = mn0; m1r = mn1;

            uint32_t ph[4][4];
            float s0 = 0.f, s1 = 0.f;
            #pragma unroll
            for (int j = 0; j < 8; j++) {
                float p0 = ex2f(S[j][0] - mn0), p1 = ex2f(S[j][1] - mn0);
                float p2 = ex2f(S[j][2] - mn1), p3 = ex2f(S[j][3] - mn1);
                s0 += p0 + p1; s1 += p2 + p3;
                int kk = j >> 1, i0 = (j & 1) * 2;
                ph[kk][i0]   = pack_h2(p0, p1);
                ph[kk][i0+1] = pack_h2(p2, p3);
            }
            s0 += __shfl_xor_sync(0xffffffffu, s0, 1);
            s0 += __shfl_xor_sync(0xffffffffu, s0, 2);
            s1 += __shfl_xor_sync(0xffffffffu, s1, 1);
            s1 += __shfl_xor_sync(0xffffffffu, s1, 2);
            l0r += s0; l1r += s1;

            {
                const int g = lane >> 3, r = lane & 7;
                #pragma unroll
                for (int kk = 0; kk < 4; kk++) {
                    #pragma unroll
                    for (int jn = 0; jn < 4; jn++) {
                        uint32_t vb[4];
                        uint32_t a = stb + AMAT
                            + (uint32_t)((kk * 16 + ((g & 1) << 3) + r) * AROWB + (2 * jn + (g >> 1)) * 16);
                        LDSM_X4T(vb, a);
                        MMA_F16(O[2*jn],   ph[kk], vb);
                        MMA_F16(O[2*jn+1], ph[kk], vb+2);
                    }
                }
            }
        }
    }

    float inv0 = 1.f / l0r, inv1 = 1.f / l1r;
    size_t orow0 = ((size_t)(b * SS + row0)) * DD + n * HD;
    size_t orow1 = orow0 + (size_t)8 * DD;
    #pragma unroll
    for (int nb = 0; nb < 8; nb++) {
        int d = nb * 8 + cl;
        *(uint32_t*)(Og + orow0 + d) = pack_h2(O[nb][0] * inv0, O[nb][1] * inv0);
        *(uint32_t*)(Og + orow1 + d) = pack_h2(O[nb][2] * inv1, O[nb][3] * inv1);
    }
}

// ---------------------------------------------------------------------------
// Fused dataflow worker, grid = 1536.
// ids [0,256)    : Q projection tiles, qb descending
// ids [256,768)  : K/V projection tiles, key rows j ascending
// ids [768,1280) : attention blocks, qb descending
// ids [1280,1536): O-projection tiles with streaming per-head waits
// ---------------------------------------------------------------------------
#define WSMEM (AQB + 3*ASTG)   // 73728 >= gemm's 61440

__global__ __launch_bounds__(256, 2) void worker(
    const __half* __restrict__ a16,
    const __half* __restrict__ wq, const __half* __restrict__ wk,
    const __half* __restrict__ wv, const __half* __restrict__ wo,
    __half* __restrict__ q16, __half* __restrict__ k16, __half* __restrict__ v16,
    __half* __restrict__ a216, float* __restrict__ out)
{
    extern __shared__ char smem[];
    const int id = blockIdx.x;
    const int tid = threadIdx.x;

    if (id < 768) {
        // ---- projection tile (criticality-ordered)
        int z, mt, ntl;
        if (id < 256) {
            int r = id >> 3;
            int qb = 15 - (r >> 1);
            int b = r & 1;
            mt = b * 16 + qb;
            z = 0;
            ntl = id & 7;
        } else {
            int u = id - 256;
            int j = u >> 5;
            int rem = u & 31;
            z = 1 + (rem >> 4);
            int sub = rem & 15;
            int b = sub >> 3;
            ntl = sub & 7;
            mt = b * 16 + j;
        }
        const __half* B = (z == 0) ? wq : (z == 1) ? wk : wv;
        __half* o16 = (z == 0) ? q16 : (z == 1) ? k16 : v16;
        gemm_body(smem, a16 + (size_t)mt * 128 * DD, B + (size_t)ntl * 128 * DD,
                  mt * 128, ntl * 128, o16, nullptr, -1);
        __syncthreads();
        __threadfence();
        if (tid == 0) atomicExch(&g_flags[z * 256 + mt * 8 + ntl], 1);
    } else if (id < 1280) {
        // ---- attention block: qb descending
        int a = id - 768;
        int qb = 15 - (a >> 5);
        int rem = a & 31;
        int b = rem >> 4, n = rem & 15;
        attn_body(smem, q16, k16, v16, a216, qb, n, b);
        __syncthreads();
        __threadfence();
        if (tid == 0) atomicExch(&g_flags[768 + (b * 16 + qb) * 16 + n], 1);
    } else {
        // ---- O-projection tile with streaming per-head dependency
        int o = id - 1280;
        int qb2 = o >> 3;
        int ntl = o & 7;
        int qb = qb2 >> 1, b = qb2 & 1;
        int mt = b * 16 + qb;
        int fbase = 768 + (b * 16 + qb) * 16;
        gemm_body(smem, a216 + (size_t)mt * 128 * DD, wo + (size_t)ntl * 128 * DD,
                  mt * 128, ntl * 128, nullptr, out, fbase);
    }
}

// ---------------------------------------------------------------------------
extern "C" void kernel_launch(void* const* d_in, const int* in_sizes, int n_in,
                              void* d_out, int out_size)
{
    const float* residual = (const float*)d_in[0];
    const float* W_Q = (const float*)d_in[1];
    const float* W_K = (const float*)d_in[2];
    const float* W_V = (const float*)d_in[3];
    const float* W_O = (const float*)d_in[4];
    float* out = (float*)d_out;

    __half *a16, *a216, *wq, *wk, *wv, *wo, *q16, *k16, *v16;
    cudaGetSymbolAddress((void**)&a16,  g_A16);
    cudaGetSymbolAddress((void**)&a216, g_A216);
    cudaGetSymbolAddress((void**)&wq,   g_WQ16);
    cudaGetSymbolAddress((void**)&wk,   g_WK16);
    cudaGetSymbolAddress((void**)&wv,   g_WV16);
    cudaGetSymbolAddress((void**)&wo,   g_WO16);
    cudaGetSymbolAddress((void**)&q16,  g_Q16);
    cudaGetSymbolAddress((void**)&k16,  g_K16);
    cudaGetSymbolAddress((void**)&v16,  g_V16);

    cudaFuncSetAttribute(worker, cudaFuncAttributeMaxDynamicSharedMemorySize, WSMEM);

    // prep + flag reset (ordering with worker guaranteed by stream order)
    prep_all<<<4608, 256>>>(residual, W_Q, W_K, W_V, W_O);

    // fused QKV -> attention -> O-projection dataflow kernel
    worker<<<1536, 256, WSMEM>>>(a16, wq, wk, wv, wo, q16, k16, v16, a216, out);
}